// round 3
// baseline (speedup 1.0000x reference)
#include <cuda_runtime.h>

// RSLDS forward-backward smoother, B=8 T=1024 N=64 K=8.
// Outputs concatenated in d_out: forward(B,T,N,K) | backward(B,T,N,K) |
// gamma1(B,T,N,K) | gamma2(B,T,N,K,K)
//
// fwbw runs the recursions UNNORMALIZED in log2 space (shift-invariant),
// anchored to state 0 each step for boundedness. Normalized outputs are
// produced by an off-critical-path lse per step.

#define FULLMASK 0xffffffffu
constexpr int B_ = 8, T_ = 1024, N_ = 64, K_ = 8;
constexpr long long BTNK = (long long)B_ * T_ * N_ * K_;

__device__ __forceinline__ float ex2f(float x) {
    float y; asm("ex2.approx.ftz.f32 %0, %1;" : "=f"(y) : "f"(x)); return y;
}
__device__ __forceinline__ float lg2f(float x) {
    float y; asm("lg2.approx.f32 %0, %1;" : "=f"(y) : "f"(x)); return y;
}

#define L2E 1.4426950408889634f
#define LN2 0.6931471805599453f

// One warp = one chain (b,n), forward or backward, serial over T with
// depth-4 register prefetch of log_a/log_b (pre-scaled to log2 units).
__global__ void __launch_bounds__(128) fwbw_kernel(
    const float* __restrict__ la,   // (B,T,N,K,K)
    const float* __restrict__ lb,   // (B,T,N,K)
    const float* __restrict__ lz,   // (N,K)
    float* __restrict__ fw,
    float* __restrict__ bw)
{
    const int w    = blockIdx.x * (blockDim.x >> 5) + (threadIdx.x >> 5);
    const int lane = threadIdx.x & 31;
    const int ii   = lane & 3;     // pair-index (j-pairs fw / i-pairs bw)
    const int rr   = lane >> 2;    // state: i (fw) or j (bw), 0..7

    const bool is_bw = (w >= B_ * N_);
    const int  c = is_bw ? w - B_ * N_ : w;
    const int  b = c / N_;
    const int  n = c % N_;
    const long long chain = (long long)b * T_ * N_ + n;  // (b,0,n) in tiles

    if (!is_bw) {
        // ---------------- forward ----------------
        // lane (i=rr, ii) handles terms j = 2*ii, 2*ii+1 of row i.
        float prev = (lz[n * K_ + rr] + lb[chain * K_ + rr]) * L2E;  // raw u' (log2)
        {   // normalized output for t=0 (off-path style, but first step anyway)
            float eo = ex2f(prev);
            eo += __shfl_xor_sync(FULLMASK, eo, 4);
            eo += __shfl_xor_sync(FULLMASK, eo, 8);
            eo += __shfl_xor_sync(FULLMASK, eo, 16);
            if (ii == 0) fw[chain * K_ + rr] = (prev - lg2f(eo)) * LN2;
        }

        float2 abuf[4];
        float  bbuf[4];
        #pragma unroll
        for (int u = 0; u < 4; u++) {
            long long bt = chain + (long long)(1 + u) * N_;
            float2 a2 = *(const float2*)(la + bt * 64 + lane * 2);
            a2.x *= L2E; a2.y *= L2E;
            abuf[u] = a2;
            bbuf[u] = lb[bt * K_ + rr] * L2E;
        }

        for (int tb = 1; tb < T_; tb += 4) {
            #pragma unroll
            for (int u = 0; u < 4; u++) {
                int t = tb + u;
                if (t >= T_) break;
                float2 av = abuf[u];
                float  bv = bbuf[u];
                int tn = t + 4;
                if (tn < T_) {
                    long long bt = chain + (long long)tn * N_;
                    float2 a2 = *(const float2*)(la + bt * 64 + lane * 2);
                    a2.x *= L2E; a2.y *= L2E;
                    abuf[u] = a2;
                    bbuf[u] = lb[bt * K_ + rr] * L2E;
                }
                // broadcasts issue back-to-back; latencies overlap
                float p0 = __shfl_sync(FULLMASK, prev, ii * 8);
                float p1 = __shfl_sync(FULLMASK, prev, ii * 8 + 4);
                float u0 = __shfl_sync(FULLMASK, prev, 0);     // anchor (state 0)
                float e = ex2f(av.x + (p0 - u0)) + ex2f(av.y + (p1 - u0));
                e += __shfl_xor_sync(FULLMASK, e, 1);
                e += __shfl_xor_sync(FULLMASK, e, 2);
                float uu = bv + lg2f(e);                        // raw, bounded
                prev = uu;
                // --- output normalization: off the recursion's critical path
                float eo = ex2f(uu);
                eo += __shfl_xor_sync(FULLMASK, eo, 4);
                eo += __shfl_xor_sync(FULLMASK, eo, 8);
                eo += __shfl_xor_sync(FULLMASK, eo, 16);
                float alpha = (uu - lg2f(eo)) * LN2;
                if (ii == 0) fw[(chain + (long long)t * N_) * K_ + rr] = alpha;
            }
        }
    } else {
        // ---------------- backward ----------------
        // lane (j=rr, ii) handles terms i = 2*ii, 2*ii+1 of column j.
        float prev = 0.0f;                                      // raw beta' (log2)
        if (ii == 0) bw[(chain + (long long)(T_ - 1) * N_) * K_ + rr] = 0.0f;

        float  c0buf[4], c1buf[4];
        float2 bbuf[4];
        #pragma unroll
        for (int u = 0; u < 4; u++) {
            int t = T_ - 2 - u;                       // uses data at t+1
            long long bt = chain + (long long)(t + 1) * N_;
            c0buf[u] = la[bt * 64 + ii * 16 + rr] * L2E;        // a[2ii][j]
            c1buf[u] = la[bt * 64 + ii * 16 + 8 + rr] * L2E;    // a[2ii+1][j]
            float2 b2 = *(const float2*)(lb + bt * K_ + ii * 2);
            b2.x *= L2E; b2.y *= L2E;
            bbuf[u]  = b2;
        }

        for (int tb = T_ - 2; tb >= 0; tb -= 4) {
            #pragma unroll
            for (int u = 0; u < 4; u++) {
                int t = tb - u;
                if (t < 0) break;
                float  cc0 = c0buf[u], cc1 = c1buf[u];
                float2 bv = bbuf[u];
                int tn = t - 4;
                if (tn >= 0) {
                    long long bt = chain + (long long)(tn + 1) * N_;
                    c0buf[u] = la[bt * 64 + ii * 16 + rr] * L2E;
                    c1buf[u] = la[bt * 64 + ii * 16 + 8 + rr] * L2E;
                    float2 b2 = *(const float2*)(lb + bt * K_ + ii * 2);
                    b2.x *= L2E; b2.y *= L2E;
                    bbuf[u]  = b2;
                }
                // s_i = beta'_{t+1}[i] + b'_{t+1}[i]; beta for state i at lane i*4
                float p0 = __shfl_sync(FULLMASK, prev, ii * 8);
                float p1 = __shfl_sync(FULLMASK, prev, ii * 8 + 4);
                float u0 = __shfl_sync(FULLMASK, prev, 0);     // anchor (state 0)
                float e = ex2f(cc0 + bv.x + (p0 - u0))
                        + ex2f(cc1 + bv.y + (p1 - u0));
                e += __shfl_xor_sync(FULLMASK, e, 1);
                e += __shfl_xor_sync(FULLMASK, e, 2);
                float uu = lg2f(e);                             // raw, bounded
                prev = uu;
                // --- output normalization: off critical path
                float eo = ex2f(uu);
                eo += __shfl_xor_sync(FULLMASK, eo, 4);
                eo += __shfl_xor_sync(FULLMASK, eo, 8);
                eo += __shfl_xor_sync(FULLMASK, eo, 16);
                float beta = (uu - lg2f(eo)) * LN2;
                if (ii == 0) bw[(chain + (long long)t * N_) * K_ + rr] = beta;
            }
        }
    }
}

// Posteriors: one warp handles 4 consecutive-n tiles at the same (b,t).
// Each 8-lane group owns one tile; lane r owns row i=r (8 j-terms).
__global__ void __launch_bounds__(256) gamma_kernel(
    const float* __restrict__ la,
    const float* __restrict__ lb,
    const float* __restrict__ fw,
    const float* __restrict__ bwp,
    float* __restrict__ g1,
    float* __restrict__ g2)
{
    const int w    = blockIdx.x * (blockDim.x >> 5) + (threadIdx.x >> 5);
    const int lane = threadIdx.x & 31;
    const int grp  = lane >> 3;
    const int r    = lane & 7;

    const int nt    = w % (N_ / 4);
    const int btile = w / (N_ / 4);
    const int t     = btile % T_;
    const int b     = btile / T_;
    const int n     = nt * 4 + grp;
    const long long base = ((long long)b * T_ + t) * N_ + n;

    const float fwv = fw[base * K_ + r];
    const float bwv = bwp[base * K_ + r];

    // gamma1 = normalize(fw + bw) over K within the 8-lane group
    float v = fwv + bwv;
    float m1 = v;
    m1 = fmaxf(m1, __shfl_xor_sync(FULLMASK, m1, 1));
    m1 = fmaxf(m1, __shfl_xor_sync(FULLMASK, m1, 2));
    m1 = fmaxf(m1, __shfl_xor_sync(FULLMASK, m1, 4));
    float e1 = __expf(v - m1);
    e1 += __shfl_xor_sync(FULLMASK, e1, 1);
    e1 += __shfl_xor_sync(FULLMASK, e1, 2);
    e1 += __shfl_xor_sync(FULLMASK, e1, 4);
    g1[base * K_ + r] = v - (m1 + __logf(e1));

    float4* g2p = (float4*)(g2 + base * 64 + r * 8);
    if (t == 0) {                       // warp-uniform branch
        float4 z = make_float4(0.f, 0.f, 0.f, 0.f);
        g2p[0] = z;
        g2p[1] = z;
        return;
    }

    const float fwp = fw[(base - N_) * K_ + r];      // forward at t-1, state r
    const float s   = bwv + lb[base * K_ + r];       // bw_t[i=r] + log_b_t[i=r]
    const float4* pa = (const float4*)(la + base * 64 + r * 8);
    float av[8];
    *(float4*)&av[0] = pa[0];
    *(float4*)&av[4] = pa[1];

    float g[8];
    #pragma unroll
    for (int j = 0; j < 8; j++)
        g[j] = av[j] + __shfl_sync(FULLMASK, fwp, j, 8) + s;

    float m = g[0];
    #pragma unroll
    for (int j = 1; j < 8; j++) m = fmaxf(m, g[j]);
    m = fmaxf(m, __shfl_xor_sync(FULLMASK, m, 1));
    m = fmaxf(m, __shfl_xor_sync(FULLMASK, m, 2));
    m = fmaxf(m, __shfl_xor_sync(FULLMASK, m, 4));
    float e = 0.f;
    #pragma unroll
    for (int j = 0; j < 8; j++) e += __expf(g[j] - m);
    e += __shfl_xor_sync(FULLMASK, e, 1);
    e += __shfl_xor_sync(FULLMASK, e, 2);
    e += __shfl_xor_sync(FULLMASK, e, 4);
    const float lse = m + __logf(e);

    float4 o0 = make_float4(g[0] - lse, g[1] - lse, g[2] - lse, g[3] - lse);
    float4 o1 = make_float4(g[4] - lse, g[5] - lse, g[6] - lse, g[7] - lse);
    g2p[0] = o0;
    g2p[1] = o1;
}

extern "C" void kernel_launch(void* const* d_in, const int* in_sizes, int n_in,
                              void* d_out, int out_size) {
    const float* la = (const float*)d_in[0];   // log_a  (B,T,N,K,K)
    const float* lb = (const float*)d_in[1];   // log_b  (B,T,N,K)
    const float* lz = (const float*)d_in[2];   // logprob_z1 (N,K)

    float* out = (float*)d_out;
    float* fw = out;
    float* bw = fw + BTNK;
    float* g1 = bw + BTNK;
    float* g2 = g1 + BTNK;

    // 1024 chain-warps (512 fw + 512 bw), 4 warps/block
    fwbw_kernel<<<(2 * B_ * N_) / 4, 128>>>(la, lb, lz, fw, bw);

    // B*T*N/4 = 131072 warps, 8 warps/block
    gamma_kernel<<<(B_ * T_ * (N_ / 4)) / 8, 256>>>(la, lb, fw, bw, g1, g2);
}

// round 5
// speedup vs baseline: 1.2631x; 1.2631x over previous
#include <cuda_runtime.h>

// RSLDS forward-backward smoother, B=8 T=1024 N=64 K=8.
// Outputs: forward(B,T,N,K) | backward(B,T,N,K) | gamma1(B,T,N,K) | gamma2(B,T,N,K,K)
//
// fwbw: unnormalized log2-space recursion (shift-invariant), anchored to
// state 0 each step. Prefetch buffers hold RAW loads (no arithmetic at load
// time — first consumption is 4 iterations later); L2E scaling folded into
// the consuming FMA. Output normalization is off the recursion's critical path.
// NO shuffles inside divergent branches (R4 bug).

#define FULLMASK 0xffffffffu
constexpr int B_ = 8, T_ = 1024, N_ = 64, K_ = 8;
constexpr long long BTNK = (long long)B_ * T_ * N_ * K_;

__device__ __forceinline__ float ex2f(float x) {
    float y; asm("ex2.approx.ftz.f32 %0, %1;" : "=f"(y) : "f"(x)); return y;
}
__device__ __forceinline__ float lg2f(float x) {
    float y; asm("lg2.approx.f32 %0, %1;" : "=f"(y) : "f"(x)); return y;
}

#define L2E 1.4426950408889634f
#define LN2 0.6931471805599453f

__global__ void __launch_bounds__(64) fwbw_kernel(
    const float* __restrict__ la,   // (B,T,N,K,K)
    const float* __restrict__ lb,   // (B,T,N,K)
    const float* __restrict__ lz,   // (N,K)
    float* __restrict__ fw,
    float* __restrict__ bw)
{
    const int w    = blockIdx.x * (blockDim.x >> 5) + (threadIdx.x >> 5);
    const int lane = threadIdx.x & 31;
    const int ii   = lane & 3;     // pair-index (j-pairs fw / i-pairs bw)
    const int rr   = lane >> 2;    // state: i (fw) or j (bw), 0..7

    const bool is_bw = (w >= B_ * N_);
    const int  c = is_bw ? w - B_ * N_ : w;
    const int  b = c / N_;
    const int  n = c % N_;
    const long long chain = (long long)b * T_ * N_ + n;  // (b,0,n) in tiles

    if (!is_bw) {
        // ---------------- forward ----------------
        // lane (i=rr, ii) handles terms j = 2*ii, 2*ii+1 of row i.
        float prev = (lz[n * K_ + rr] + lb[chain * K_ + rr]) * L2E;  // log2 units
        {
            // all shuffles CONVERGENT; only the store is predicated
            float u0i = __shfl_sync(FULLMASK, prev, 0);
            float po  = prev - u0i;
            float eo  = ex2f(po);
            eo += __shfl_xor_sync(FULLMASK, eo, 4);
            eo += __shfl_xor_sync(FULLMASK, eo, 8);
            eo += __shfl_xor_sync(FULLMASK, eo, 16);
            float a0 = (po - lg2f(eo)) * LN2;
            if (ii == 0) fw[chain * K_ + rr] = a0;
        }

        float2 abuf[4];       // RAW ln-units, untouched until consumption
        float  bbuf[4];
        #pragma unroll
        for (int u = 0; u < 4; u++) {
            long long bt = chain + (long long)(1 + u) * N_;
            abuf[u] = *(const float2*)(la + bt * 64 + lane * 2);
            bbuf[u] = lb[bt * K_ + rr];
        }

        for (int tb = 1; tb < T_; tb += 4) {
            #pragma unroll
            for (int u = 0; u < 4; u++) {
                int t = tb + u;
                if (t >= T_) break;
                float2 av = abuf[u];
                float  bv = bbuf[u];
                int tn = t + 4;
                if (tn < T_) {
                    long long bt = chain + (long long)tn * N_;
                    abuf[u] = *(const float2*)(la + bt * 64 + lane * 2);
                    bbuf[u] = lb[bt * K_ + rr];
                }
                float p0 = __shfl_sync(FULLMASK, prev, ii * 8);
                float p1 = __shfl_sync(FULLMASK, prev, ii * 8 + 4);
                float u0 = __shfl_sync(FULLMASK, prev, 0);      // anchor
                float e = ex2f(fmaf(av.x, L2E, p0 - u0))
                        + ex2f(fmaf(av.y, L2E, p1 - u0));
                e += __shfl_xor_sync(FULLMASK, e, 1);
                e += __shfl_xor_sync(FULLMASK, e, 2);
                float uu = fmaf(bv, L2E, lg2f(e));              // raw, bounded
                prev = uu;
                // off-critical-path normalized output (no shfl under predication)
                float eo = ex2f(uu);
                eo += __shfl_xor_sync(FULLMASK, eo, 4);
                eo += __shfl_xor_sync(FULLMASK, eo, 8);
                eo += __shfl_xor_sync(FULLMASK, eo, 16);
                float alpha = (uu - lg2f(eo)) * LN2;
                if (ii == 0)
                    fw[(chain + (long long)t * N_) * K_ + rr] = alpha;
            }
        }
    } else {
        // ---------------- backward ----------------
        // lane (j=rr, ii) handles terms i = 2*ii, 2*ii+1 of column j.
        float prev = 0.0f;
        if (ii == 0) bw[(chain + (long long)(T_ - 1) * N_) * K_ + rr] = 0.0f;

        float  c0buf[4], c1buf[4];   // RAW
        float2 bbuf[4];
        #pragma unroll
        for (int u = 0; u < 4; u++) {
            int t = T_ - 2 - u;                       // uses data at t+1
            long long bt = chain + (long long)(t + 1) * N_;
            c0buf[u] = la[bt * 64 + ii * 16 + rr];        // a[2ii][j]
            c1buf[u] = la[bt * 64 + ii * 16 + 8 + rr];    // a[2ii+1][j]
            bbuf[u]  = *(const float2*)(lb + bt * K_ + ii * 2);
        }

        for (int tb = T_ - 2; tb >= 0; tb -= 4) {
            #pragma unroll
            for (int u = 0; u < 4; u++) {
                int t = tb - u;
                if (t < 0) break;
                float  cc0 = c0buf[u], cc1 = c1buf[u];
                float2 bv = bbuf[u];
                int tn = t - 4;
                if (tn >= 0) {
                    long long bt = chain + (long long)(tn + 1) * N_;
                    c0buf[u] = la[bt * 64 + ii * 16 + rr];
                    c1buf[u] = la[bt * 64 + ii * 16 + 8 + rr];
                    bbuf[u]  = *(const float2*)(lb + bt * K_ + ii * 2);
                }
                float p0 = __shfl_sync(FULLMASK, prev, ii * 8);
                float p1 = __shfl_sync(FULLMASK, prev, ii * 8 + 4);
                float u0 = __shfl_sync(FULLMASK, prev, 0);      // anchor
                float e = ex2f(fmaf(cc0 + bv.x, L2E, p0 - u0))
                        + ex2f(fmaf(cc1 + bv.y, L2E, p1 - u0));
                e += __shfl_xor_sync(FULLMASK, e, 1);
                e += __shfl_xor_sync(FULLMASK, e, 2);
                float uu = lg2f(e);                             // raw, bounded
                prev = uu;
                // off-critical-path normalized output
                float eo = ex2f(uu);
                eo += __shfl_xor_sync(FULLMASK, eo, 4);
                eo += __shfl_xor_sync(FULLMASK, eo, 8);
                eo += __shfl_xor_sync(FULLMASK, eo, 16);
                float beta = (uu - lg2f(eo)) * LN2;
                if (ii == 0)
                    bw[(chain + (long long)t * N_) * K_ + rr] = beta;
            }
        }
    }
}

// Posteriors: one warp handles 4 consecutive-n tiles at the same (b,t).
// Each 8-lane group owns one tile; lane r owns row i=r (8 j-terms).
__global__ void __launch_bounds__(256) gamma_kernel(
    const float* __restrict__ la,
    const float* __restrict__ lb,
    const float* __restrict__ fw,
    const float* __restrict__ bwp,
    float* __restrict__ g1,
    float* __restrict__ g2)
{
    const int w    = blockIdx.x * (blockDim.x >> 5) + (threadIdx.x >> 5);
    const int lane = threadIdx.x & 31;
    const int grp  = lane >> 3;
    const int r    = lane & 7;

    const int nt    = w % (N_ / 4);
    const int btile = w / (N_ / 4);
    const int t     = btile % T_;
    const int b     = btile / T_;
    const int n     = nt * 4 + grp;
    const long long base = ((long long)b * T_ + t) * N_ + n;

    const float fwv = fw[base * K_ + r];
    const float bwv = bwp[base * K_ + r];

    // gamma1 = normalize(fw + bw) over K within the 8-lane group
    float v = fwv + bwv;
    float m1 = v;
    m1 = fmaxf(m1, __shfl_xor_sync(FULLMASK, m1, 1));
    m1 = fmaxf(m1, __shfl_xor_sync(FULLMASK, m1, 2));
    m1 = fmaxf(m1, __shfl_xor_sync(FULLMASK, m1, 4));
    float e1 = __expf(v - m1);
    e1 += __shfl_xor_sync(FULLMASK, e1, 1);
    e1 += __shfl_xor_sync(FULLMASK, e1, 2);
    e1 += __shfl_xor_sync(FULLMASK, e1, 4);
    g1[base * K_ + r] = v - (m1 + __logf(e1));

    float4* g2p = (float4*)(g2 + base * 64 + r * 8);
    if (t == 0) {                       // warp-uniform branch
        float4 z = make_float4(0.f, 0.f, 0.f, 0.f);
        g2p[0] = z;
        g2p[1] = z;
        return;
    }

    const float fwp = fw[(base - N_) * K_ + r];      // forward at t-1, state r
    const float s   = bwv + lb[base * K_ + r];       // bw_t[i=r] + log_b_t[i=r]
    const float4* pa = (const float4*)(la + base * 64 + r * 8);
    float av[8];
    *(float4*)&av[0] = pa[0];
    *(float4*)&av[4] = pa[1];

    float g[8];
    #pragma unroll
    for (int j = 0; j < 8; j++)
        g[j] = av[j] + __shfl_sync(FULLMASK, fwp, j, 8) + s;

    float m = g[0];
    #pragma unroll
    for (int j = 1; j < 8; j++) m = fmaxf(m, g[j]);
    m = fmaxf(m, __shfl_xor_sync(FULLMASK, m, 1));
    m = fmaxf(m, __shfl_xor_sync(FULLMASK, m, 2));
    m = fmaxf(m, __shfl_xor_sync(FULLMASK, m, 4));
    float e = 0.f;
    #pragma unroll
    for (int j = 0; j < 8; j++) e += __expf(g[j] - m);
    e += __shfl_xor_sync(FULLMASK, e, 1);
    e += __shfl_xor_sync(FULLMASK, e, 2);
    e += __shfl_xor_sync(FULLMASK, e, 4);
    const float lse = m + __logf(e);

    float4 o0 = make_float4(g[0] - lse, g[1] - lse, g[2] - lse, g[3] - lse);
    float4 o1 = make_float4(g[4] - lse, g[5] - lse, g[6] - lse, g[7] - lse);
    g2p[0] = o0;
    g2p[1] = o1;
}

extern "C" void kernel_launch(void* const* d_in, const int* in_sizes, int n_in,
                              void* d_out, int out_size) {
    const float* la = (const float*)d_in[0];   // log_a  (B,T,N,K,K)
    const float* lb = (const float*)d_in[1];   // log_b  (B,T,N,K)
    const float* lz = (const float*)d_in[2];   // logprob_z1 (N,K)

    float* out = (float*)d_out;
    float* fw = out;
    float* bw = fw + BTNK;
    float* g1 = bw + BTNK;
    float* g2 = g1 + BTNK;

    // 1024 chain-warps (512 fw + 512 bw), 2 warps/block for fine balance
    fwbw_kernel<<<(2 * B_ * N_) / 2, 64>>>(la, lb, lz, fw, bw);

    // B*T*N/4 = 131072 warps, 8 warps/block
    gamma_kernel<<<(B_ * T_ * (N_ / 4)) / 8, 256>>>(la, lb, fw, bw, g1, g2);
}

// round 6
// speedup vs baseline: 2.3077x; 1.8270x over previous
#include <cuda_runtime.h>

// RSLDS forward-backward smoother, B=8 T=1024 N=64 K=8.
// Outputs: forward | backward | gamma1 | gamma2 (concatenated in d_out).
//
// Blocked-scan decomposition (recursion is linear in probability space):
//   pass1: per-(chain,segment) 8x8 transfer-matrix products (linear, max-rescaled)
//   pass2: short sequential scan over 32 segments -> boundary vectors
//   pass3: per-segment 32-step log-space recursion (identical math to the
//          previously passing kernel), massively parallel
//   gamma: unchanged posterior kernel (already ~73% DRAM).

#define FULLMASK 0xffffffffu
constexpr int B_ = 8, T_ = 1024, N_ = 64, K_ = 8;
constexpr int C_ = B_ * N_;          // 512 chains
constexpr int L_ = 32, S_ = 32;      // segment length, count
constexpr long long BTNK = (long long)B_ * T_ * N_ * K_;

__device__ float g_Q [C_ * S_ * 64];   // segment transfer matrices (linear, rescaled)
__device__ float g_Vb[C_ * S_ * 8];    // fw boundaries: v_s = alpha_{s*L-1}, s=1..31
__device__ float g_Rb[C_ * S_ * 8];    // bw boundaries: r_s = beta_{s*L-1},  s=1..31

__device__ __forceinline__ float ex2f(float x) {
    float y; asm("ex2.approx.ftz.f32 %0, %1;" : "=f"(y) : "f"(x)); return y;
}
__device__ __forceinline__ float lg2f(float x) {
    float y; asm("lg2.approx.f32 %0, %1;" : "=f"(y) : "f"(x)); return y;
}
__device__ __forceinline__ float rcpf(float x) {
    float y; asm("rcp.approx.ftz.f32 %0, %1;" : "=f"(y) : "f"(x)); return y;
}

#define L2E 1.4426950408889634f
#define LN2 0.6931471805599453f

// ---------------------------------------------------------------------------
// pass1: Q_s = M_te ... M_ts  (M_t[i,j] = exp(log_b_t[i] + log_a_t[i,j]))
// lane (i = lane>>2, q = lane&3) holds Q[i,2q], Q[i,2q+1].
// ---------------------------------------------------------------------------
__global__ void __launch_bounds__(128) pass1_kernel(
    const float* __restrict__ la, const float* __restrict__ lb)
{
    const int w    = blockIdx.x * 4 + (threadIdx.x >> 5);
    const int lane = threadIdx.x & 31;
    const int q    = lane & 3;
    const int i    = lane >> 2;
    const int c = w >> 5, s = w & 31;
    const int b = c >> 6, n = c & 63;
    const long long tile0 = (long long)b * (T_ * N_) + n;

    const int ts = (s == 0) ? 1 : s * L_;
    const int te = s * L_ + L_ - 1;

    float Qx, Qy;
    {   // first step: Q = M_ts (lane's own entries are exactly mt[i,2q],mt[i,2q+1])
        long long tl = tile0 + (long long)ts * N_;
        float2 a2 = *(const float2*)(la + tl * 64 + lane * 2);
        float bi  = lb[tl * 8 + i];
        Qx = ex2f((a2.x + bi) * L2E);
        Qy = ex2f((a2.y + bi) * L2E);
    }

    for (int t = ts + 1; t <= te; t++) {
        long long tl = tile0 + (long long)t * N_;
        float2 a2 = *(const float2*)(la + tl * 64 + lane * 2);
        float bi  = lb[tl * 8 + i];
        float mtx = ex2f((a2.x + bi) * L2E);   // mt[i,2q]
        float mty = ex2f((a2.y + bi) * L2E);   // mt[i,2q+1]

        float nx = 0.f, ny = 0.f;
        #pragma unroll
        for (int j2 = 0; j2 < 4; j2++) {
            // mt row i gathered within the 4-lane group
            float ma = __shfl_sync(FULLMASK, mtx, j2, 4);      // mt[i,2j2]
            float mb = __shfl_sync(FULLMASK, mty, j2, 4);      // mt[i,2j2+1]
            // Q rows 2j2, 2j2+1 at columns 2q, 2q+1
            float qxa = __shfl_sync(FULLMASK, Qx, 8 * j2 + q);       // Q[2j2,2q]
            float qya = __shfl_sync(FULLMASK, Qy, 8 * j2 + q);       // Q[2j2,2q+1]
            float qxb = __shfl_sync(FULLMASK, Qx, 8 * j2 + 4 + q);   // Q[2j2+1,2q]
            float qyb = __shfl_sync(FULLMASK, Qy, 8 * j2 + 4 + q);   // Q[2j2+1,2q+1]
            nx = fmaf(ma, qxa, fmaf(mb, qxb, nx));
            ny = fmaf(ma, qya, fmaf(mb, qyb, ny));
        }
        // rescale by max entry (scale cancels in all normalized outputs)
        float m = fmaxf(nx, ny);
        m = fmaxf(m, __shfl_xor_sync(FULLMASK, m, 1));
        m = fmaxf(m, __shfl_xor_sync(FULLMASK, m, 2));
        m = fmaxf(m, __shfl_xor_sync(FULLMASK, m, 4));
        m = fmaxf(m, __shfl_xor_sync(FULLMASK, m, 8));
        m = fmaxf(m, __shfl_xor_sync(FULLMASK, m, 16));
        float inv = rcpf(m);
        Qx = nx * inv;
        Qy = ny * inv;
    }
    *(float2*)(g_Q + (size_t)(c * S_ + s) * 64 + lane * 2) = make_float2(Qx, Qy);
}

// ---------------------------------------------------------------------------
// pass2: sequential scan over segments. warp = (dir, chain).
// fw: v_{s+1} = Q_s v_s  (v_1..v_31 stored);  bw: r_s = Q_s^T r_{s+1} (r_31..r_1)
// ---------------------------------------------------------------------------
__global__ void __launch_bounds__(128) pass2_kernel(
    const float* __restrict__ lb, const float* __restrict__ lz)
{
    const int w    = blockIdx.x * 4 + (threadIdx.x >> 5);
    const int lane = threadIdx.x & 31;
    const int q    = lane & 3;
    const int i    = lane >> 2;
    const bool is_bw = (w >= C_);
    const int c = is_bw ? w - C_ : w;
    const int b = c >> 6, n = c & 63;
    const long long tile0 = (long long)b * (T_ * N_) + n;

    if (!is_bw) {
        // v = alpha_hat_0 (max-anchored linear)
        float x = lz[n * 8 + i] + lb[tile0 * 8 + i];
        float m0 = x;
        m0 = fmaxf(m0, __shfl_xor_sync(FULLMASK, m0, 4));
        m0 = fmaxf(m0, __shfl_xor_sync(FULLMASK, m0, 8));
        m0 = fmaxf(m0, __shfl_xor_sync(FULLMASK, m0, 16));
        float vi = ex2f((x - m0) * L2E);       // v[i], replicated over q

        for (int s = 0; s <= 30; s++) {
            float2 Qr = *(const float2*)(g_Q + (size_t)(c * S_ + s) * 64 + lane * 2);
            float vx = __shfl_sync(FULLMASK, vi, 8 * q);        // v[2q]
            float vy = __shfl_sync(FULLMASK, vi, 8 * q + 4);    // v[2q+1]
            float p = fmaf(Qr.x, vx, Qr.y * vy);
            p += __shfl_xor_sync(FULLMASK, p, 1);
            p += __shfl_xor_sync(FULLMASK, p, 2);               // new[i] in group
            float m = p;
            m = fmaxf(m, __shfl_xor_sync(FULLMASK, m, 4));
            m = fmaxf(m, __shfl_xor_sync(FULLMASK, m, 8));
            m = fmaxf(m, __shfl_xor_sync(FULLMASK, m, 16));
            vi = p * rcpf(m);
            if (q == 0) g_Vb[(size_t)(c * S_ + s + 1) * 8 + i] = vi;
        }
    } else {
        float ri = 1.0f;                        // beta_1023 = ones (linear)
        for (int s = 31; s >= 1; s--) {
            float2 Qr = *(const float2*)(g_Q + (size_t)(c * S_ + s) * 64 + lane * 2);
            float pe = Qr.x * ri;               // contribution to new[2q]
            float po = Qr.y * ri;               // contribution to new[2q+1]
            pe += __shfl_xor_sync(FULLMASK, pe, 4);
            pe += __shfl_xor_sync(FULLMASK, pe, 8);
            pe += __shfl_xor_sync(FULLMASK, pe, 16);
            po += __shfl_xor_sync(FULLMASK, po, 4);
            po += __shfl_xor_sync(FULLMASK, po, 8);
            po += __shfl_xor_sync(FULLMASK, po, 16);
            float re = __shfl_sync(FULLMASK, pe, i >> 1);       // new[2*(i>>1)]
            float ro = __shfl_sync(FULLMASK, po, i >> 1);       // new[2*(i>>1)+1]
            float rn = (i & 1) ? ro : re;                       // new[i]
            float m = fmaxf(pe, po);
            m = fmaxf(m, __shfl_xor_sync(FULLMASK, m, 1));
            m = fmaxf(m, __shfl_xor_sync(FULLMASK, m, 2));
            ri = rn * rcpf(m);
            if (q == 0) g_Rb[(size_t)(c * S_ + s) * 8 + i] = ri;
        }
    }
}

// ---------------------------------------------------------------------------
// pass3 fw: warp = (chain, segment); 32-step log2-space recursion (R5 math).
// lane (i=rr, ii) handles j-pair 2ii,2ii+1 of row i.
// ---------------------------------------------------------------------------
__global__ void __launch_bounds__(128) pass3_fw_kernel(
    const float* __restrict__ la, const float* __restrict__ lb,
    const float* __restrict__ lz, float* __restrict__ fw)
{
    const int w    = blockIdx.x * 4 + (threadIdx.x >> 5);
    const int lane = threadIdx.x & 31;
    const int ii   = lane & 3;
    const int rr   = lane >> 2;
    const int c = w >> 5, s = w & 31;
    const int b = c >> 6, n = c & 63;
    const long long tile0 = (long long)b * (T_ * N_) + n;

    float prev;
    int t0;
    if (s == 0) {
        prev = (lz[n * 8 + rr] + lb[tile0 * 8 + rr]) * L2E;
        float u0 = __shfl_sync(FULLMASK, prev, 0);
        float po = prev - u0;
        float eo = ex2f(po);
        eo += __shfl_xor_sync(FULLMASK, eo, 4);
        eo += __shfl_xor_sync(FULLMASK, eo, 8);
        eo += __shfl_xor_sync(FULLMASK, eo, 16);
        float a0 = (po - lg2f(eo)) * LN2;
        if (ii == 0) fw[tile0 * 8 + rr] = a0;
        t0 = 1;
    } else {
        prev = lg2f(g_Vb[(size_t)(c * S_ + s) * 8 + rr]);   // alpha_{s*L-1}
        t0 = s * L_;
    }
    const int t1 = s * L_ + L_ - 1;

    for (int t = t0; t <= t1; t++) {
        long long tl = tile0 + (long long)t * N_;
        float2 av = *(const float2*)(la + tl * 64 + lane * 2);
        float  bv = lb[tl * 8 + rr];
        float p0 = __shfl_sync(FULLMASK, prev, ii * 8);
        float p1 = __shfl_sync(FULLMASK, prev, ii * 8 + 4);
        float u0 = __shfl_sync(FULLMASK, prev, 0);
        float e = ex2f(fmaf(av.x, L2E, p0 - u0))
                + ex2f(fmaf(av.y, L2E, p1 - u0));
        e += __shfl_xor_sync(FULLMASK, e, 1);
        e += __shfl_xor_sync(FULLMASK, e, 2);
        float uu = fmaf(bv, L2E, lg2f(e));
        prev = uu;
        float eo = ex2f(uu);
        eo += __shfl_xor_sync(FULLMASK, eo, 4);
        eo += __shfl_xor_sync(FULLMASK, eo, 8);
        eo += __shfl_xor_sync(FULLMASK, eo, 16);
        float alpha = (uu - lg2f(eo)) * LN2;
        if (ii == 0) fw[tl * 8 + rr] = alpha;
    }
}

// ---------------------------------------------------------------------------
// pass3 bw: lane (j=rr, ii) handles i-pair 2ii,2ii+1 of column j.
// ---------------------------------------------------------------------------
__global__ void __launch_bounds__(128) pass3_bw_kernel(
    const float* __restrict__ la, const float* __restrict__ lb,
    float* __restrict__ bw)
{
    const int w    = blockIdx.x * 4 + (threadIdx.x >> 5);
    const int lane = threadIdx.x & 31;
    const int ii   = lane & 3;
    const int rr   = lane >> 2;
    const int c = w >> 5, s = w & 31;
    const int b = c >> 6, n = c & 63;
    const long long tile0 = (long long)b * (T_ * N_) + n;

    float prev;
    if (s == 31) {
        prev = 0.0f;                                     // beta_1023 (raw zeros)
        if (ii == 0) bw[(tile0 + 1023LL * N_) * 8 + rr] = 0.0f;
    } else {
        prev = lg2f(g_Rb[(size_t)(c * S_ + s + 1) * 8 + rr]);  // beta_{sL+31}
        float u0 = __shfl_sync(FULLMASK, prev, 0);
        float po = prev - u0;
        float eo = ex2f(po);
        eo += __shfl_xor_sync(FULLMASK, eo, 4);
        eo += __shfl_xor_sync(FULLMASK, eo, 8);
        eo += __shfl_xor_sync(FULLMASK, eo, 16);
        float bout = (po - lg2f(eo)) * LN2;
        if (ii == 0) bw[(tile0 + (long long)(s * L_ + L_ - 1) * N_) * 8 + rr] = bout;
    }

    for (int t = s * L_ + L_ - 2; t >= s * L_; t--) {
        long long tl = tile0 + (long long)(t + 1) * N_;
        float c0 = la[tl * 64 + ii * 16 + rr];           // a_{t+1}[2ii][j]
        float c1 = la[tl * 64 + ii * 16 + 8 + rr];       // a_{t+1}[2ii+1][j]
        float2 bv = *(const float2*)(lb + tl * 8 + ii * 2);
        float p0 = __shfl_sync(FULLMASK, prev, ii * 8);
        float p1 = __shfl_sync(FULLMASK, prev, ii * 8 + 4);
        float u0 = __shfl_sync(FULLMASK, prev, 0);
        float e = ex2f(fmaf(c0 + bv.x, L2E, p0 - u0))
                + ex2f(fmaf(c1 + bv.y, L2E, p1 - u0));
        e += __shfl_xor_sync(FULLMASK, e, 1);
        e += __shfl_xor_sync(FULLMASK, e, 2);
        float uu = lg2f(e);
        prev = uu;
        float eo = ex2f(uu);
        eo += __shfl_xor_sync(FULLMASK, eo, 4);
        eo += __shfl_xor_sync(FULLMASK, eo, 8);
        eo += __shfl_xor_sync(FULLMASK, eo, 16);
        float beta = (uu - lg2f(eo)) * LN2;
        if (ii == 0) bw[(tile0 + (long long)t * N_) * 8 + rr] = beta;
    }
}

// ---------------------------------------------------------------------------
// gamma: unchanged (73% DRAM). One warp = 4 (b,t,n) tiles.
// ---------------------------------------------------------------------------
__global__ void __launch_bounds__(256) gamma_kernel(
    const float* __restrict__ la,
    const float* __restrict__ lb,
    const float* __restrict__ fw,
    const float* __restrict__ bwp,
    float* __restrict__ g1,
    float* __restrict__ g2)
{
    const int w    = blockIdx.x * (blockDim.x >> 5) + (threadIdx.x >> 5);
    const int lane = threadIdx.x & 31;
    const int grp  = lane >> 3;
    const int r    = lane & 7;

    const int nt    = w % (N_ / 4);
    const int btile = w / (N_ / 4);
    const int t     = btile % T_;
    const int b     = btile / T_;
    const int n     = nt * 4 + grp;
    const long long base = ((long long)b * T_ + t) * N_ + n;

    const float fwv = fw[base * K_ + r];
    const float bwv = bwp[base * K_ + r];

    float v = fwv + bwv;
    float m1 = v;
    m1 = fmaxf(m1, __shfl_xor_sync(FULLMASK, m1, 1));
    m1 = fmaxf(m1, __shfl_xor_sync(FULLMASK, m1, 2));
    m1 = fmaxf(m1, __shfl_xor_sync(FULLMASK, m1, 4));
    float e1 = __expf(v - m1);
    e1 += __shfl_xor_sync(FULLMASK, e1, 1);
    e1 += __shfl_xor_sync(FULLMASK, e1, 2);
    e1 += __shfl_xor_sync(FULLMASK, e1, 4);
    g1[base * K_ + r] = v - (m1 + __logf(e1));

    float4* g2p = (float4*)(g2 + base * 64 + r * 8);
    if (t == 0) {
        float4 z = make_float4(0.f, 0.f, 0.f, 0.f);
        g2p[0] = z;
        g2p[1] = z;
        return;
    }

    const float fwp = fw[(base - N_) * K_ + r];
    const float s   = bwv + lb[base * K_ + r];
    const float4* pa = (const float4*)(la + base * 64 + r * 8);
    float av[8];
    *(float4*)&av[0] = pa[0];
    *(float4*)&av[4] = pa[1];

    float g[8];
    #pragma unroll
    for (int j = 0; j < 8; j++)
        g[j] = av[j] + __shfl_sync(FULLMASK, fwp, j, 8) + s;

    float m = g[0];
    #pragma unroll
    for (int j = 1; j < 8; j++) m = fmaxf(m, g[j]);
    m = fmaxf(m, __shfl_xor_sync(FULLMASK, m, 1));
    m = fmaxf(m, __shfl_xor_sync(FULLMASK, m, 2));
    m = fmaxf(m, __shfl_xor_sync(FULLMASK, m, 4));
    float e = 0.f;
    #pragma unroll
    for (int j = 0; j < 8; j++) e += __expf(g[j] - m);
    e += __shfl_xor_sync(FULLMASK, e, 1);
    e += __shfl_xor_sync(FULLMASK, e, 2);
    e += __shfl_xor_sync(FULLMASK, e, 4);
    const float lse = m + __logf(e);

    float4 o0 = make_float4(g[0] - lse, g[1] - lse, g[2] - lse, g[3] - lse);
    float4 o1 = make_float4(g[4] - lse, g[5] - lse, g[6] - lse, g[7] - lse);
    g2p[0] = o0;
    g2p[1] = o1;
}

extern "C" void kernel_launch(void* const* d_in, const int* in_sizes, int n_in,
                              void* d_out, int out_size) {
    const float* la = (const float*)d_in[0];   // log_a  (B,T,N,K,K)
    const float* lb = (const float*)d_in[1];   // log_b  (B,T,N,K)
    const float* lz = (const float*)d_in[2];   // logprob_z1 (N,K)

    float* out = (float*)d_out;
    float* fw = out;
    float* bw = fw + BTNK;
    float* g1 = bw + BTNK;
    float* g2 = g1 + BTNK;

    pass1_kernel<<<(C_ * S_) / 4, 128>>>(la, lb);            // 16384 warps
    pass2_kernel<<<(2 * C_) / 4, 128>>>(lb, lz);             // 1024 warps
    pass3_fw_kernel<<<(C_ * S_) / 4, 128>>>(la, lb, lz, fw); // 16384 warps
    pass3_bw_kernel<<<(C_ * S_) / 4, 128>>>(la, lb, bw);     // 16384 warps
    gamma_kernel<<<(B_ * T_ * (N_ / 4)) / 8, 256>>>(la, lb, fw, bw, g1, g2);
}

// round 7
// speedup vs baseline: 3.6049x; 1.5621x over previous
#include <cuda_runtime.h>

// RSLDS forward-backward smoother, B=8 T=1024 N=64 K=8.
// Outputs: forward | backward | gamma1 | gamma2 (concatenated in d_out).
//
// Blocked scan:
//   pass1: per-(chain,segment) 8x8 transfer-matrix products (linear, rescaled every 4 steps)
//   pass2: sequential scan over 32 segments -> boundary vectors
//   pass3: per-segment 32-step log2-space recursion -> UNNORMALIZED anchored
//          values in device scratch (normalization deferred: shift-invariant)
//   gamma: normalizes fw/bw (writing final outputs) + gamma1 + gamma2.

#define FULLMASK 0xffffffffu
constexpr int B_ = 8, T_ = 1024, N_ = 64, K_ = 8;
constexpr int C_ = B_ * N_;          // 512 chains
constexpr int L_ = 32, S_ = 32;      // segment length, count
constexpr int TN = T_ * N_;
constexpr long long BTNK = (long long)B_ * T_ * N_ * K_;

__device__ float g_Q  [C_ * S_ * 64];  // segment transfer matrices (linear)
__device__ float g_Vb [C_ * S_ * 8];   // fw boundaries (linear, rescaled)
__device__ float g_Rb [C_ * S_ * 8];   // bw boundaries (linear, rescaled)
__device__ float g_fwu[BTNK];          // unnormalized log2 alpha'
__device__ float g_bwu[BTNK];          // unnormalized log2 beta'

__device__ __forceinline__ float ex2f(float x) {
    float y; asm("ex2.approx.ftz.f32 %0, %1;" : "=f"(y) : "f"(x)); return y;
}
__device__ __forceinline__ float lg2f(float x) {
    float y; asm("lg2.approx.f32 %0, %1;" : "=f"(y) : "f"(x)); return y;
}
__device__ __forceinline__ float rcpf(float x) {
    float y; asm("rcp.approx.ftz.f32 %0, %1;" : "=f"(y) : "f"(x)); return y;
}

#define L2E 1.4426950408889634f
#define LN2 0.6931471805599453f

// ---------------------------------------------------------------------------
// pass1: Q_s = M_te ... M_ts,  M_t[i,j] = exp(log_b_t[i] + log_a_t[i,j]).
// lane (i = lane>>2, q = lane&3) holds Q[i,2q], Q[i,2q+1]. Rescale every 4 steps.
// ---------------------------------------------------------------------------
__global__ void __launch_bounds__(128) pass1_kernel(
    const float* __restrict__ la, const float* __restrict__ lb)
{
    const int w    = blockIdx.x * 4 + (threadIdx.x >> 5);
    const int lane = threadIdx.x & 31;
    const int q    = lane & 3;
    const int i    = lane >> 2;
    const int c = w >> 5, s = w & 31;
    const int b = c >> 6, n = c & 63;
    const int tile0 = b * TN + n;

    const int ts = (s == 0) ? 1 : s * L_;
    const int te = s * L_ + L_ - 1;

    const float2* ap = (const float2*)la + (tile0 + ts * N_) * 32 + lane;
    const float*  bp = lb + (tile0 + ts * N_) * 8 + i;

    float Qx, Qy;
    {   // Q = M_ts
        float2 a2 = *ap;
        float  bi = *bp;
        Qx = ex2f((a2.x + bi) * L2E);
        Qy = ex2f((a2.y + bi) * L2E);
        ap += 32 * N_; bp += 8 * N_;
    }

    int cnt = 0;
    for (int t = ts + 1; t <= te; t++) {
        float2 a2 = *ap;
        float  bi = *bp;
        ap += 32 * N_; bp += 8 * N_;
        float mtx = ex2f((a2.x + bi) * L2E);   // mt[i,2q]
        float mty = ex2f((a2.y + bi) * L2E);   // mt[i,2q+1]

        float nx = 0.f, ny = 0.f;
        #pragma unroll
        for (int j2 = 0; j2 < 4; j2++) {
            float ma = __shfl_sync(FULLMASK, mtx, j2, 4);          // mt[i,2j2]
            float mb = __shfl_sync(FULLMASK, mty, j2, 4);          // mt[i,2j2+1]
            float qxa = __shfl_sync(FULLMASK, Qx, 8 * j2 + q);     // Q[2j2,2q]
            float qya = __shfl_sync(FULLMASK, Qy, 8 * j2 + q);     // Q[2j2,2q+1]
            float qxb = __shfl_sync(FULLMASK, Qx, 8 * j2 + 4 + q); // Q[2j2+1,2q]
            float qyb = __shfl_sync(FULLMASK, Qy, 8 * j2 + 4 + q); // Q[2j2+1,2q+1]
            nx = fmaf(ma, qxa, fmaf(mb, qxb, nx));
            ny = fmaf(ma, qya, fmaf(mb, qyb, ny));
        }
        Qx = nx; Qy = ny;
        if ((++cnt & 3) == 0 || t == te) {     // rescale every 4 steps + final
            float m = fmaxf(Qx, Qy);
            m = fmaxf(m, __shfl_xor_sync(FULLMASK, m, 1));
            m = fmaxf(m, __shfl_xor_sync(FULLMASK, m, 2));
            m = fmaxf(m, __shfl_xor_sync(FULLMASK, m, 4));
            m = fmaxf(m, __shfl_xor_sync(FULLMASK, m, 8));
            m = fmaxf(m, __shfl_xor_sync(FULLMASK, m, 16));
            float inv = rcpf(m);
            Qx *= inv; Qy *= inv;
        }
    }
    *(float2*)(g_Q + (size_t)(c * S_ + s) * 64 + lane * 2) = make_float2(Qx, Qy);
}

// ---------------------------------------------------------------------------
// pass2: sequential scan over segments. warp = (dir, chain). Unchanged math.
// ---------------------------------------------------------------------------
__global__ void __launch_bounds__(128) pass2_kernel(
    const float* __restrict__ lb, const float* __restrict__ lz)
{
    const int w    = blockIdx.x * 4 + (threadIdx.x >> 5);
    const int lane = threadIdx.x & 31;
    const int q    = lane & 3;
    const int i    = lane >> 2;
    const bool is_bw = (w >= C_);
    const int c = is_bw ? w - C_ : w;
    const int b = c >> 6, n = c & 63;
    const int tile0 = b * TN + n;

    if (!is_bw) {
        float x = lz[n * 8 + i] + lb[tile0 * 8 + i];
        float m0 = x;
        m0 = fmaxf(m0, __shfl_xor_sync(FULLMASK, m0, 4));
        m0 = fmaxf(m0, __shfl_xor_sync(FULLMASK, m0, 8));
        m0 = fmaxf(m0, __shfl_xor_sync(FULLMASK, m0, 16));
        float vi = ex2f((x - m0) * L2E);       // v[i], replicated over q

        for (int s = 0; s <= 30; s++) {
            float2 Qr = *(const float2*)(g_Q + (size_t)(c * S_ + s) * 64 + lane * 2);
            float vx = __shfl_sync(FULLMASK, vi, 8 * q);
            float vy = __shfl_sync(FULLMASK, vi, 8 * q + 4);
            float p = fmaf(Qr.x, vx, Qr.y * vy);
            p += __shfl_xor_sync(FULLMASK, p, 1);
            p += __shfl_xor_sync(FULLMASK, p, 2);
            float m = p;
            m = fmaxf(m, __shfl_xor_sync(FULLMASK, m, 4));
            m = fmaxf(m, __shfl_xor_sync(FULLMASK, m, 8));
            m = fmaxf(m, __shfl_xor_sync(FULLMASK, m, 16));
            vi = p * rcpf(m);
            if (q == 0) g_Vb[(size_t)(c * S_ + s + 1) * 8 + i] = vi;
        }
    } else {
        float ri = 1.0f;
        for (int s = 31; s >= 1; s--) {
            float2 Qr = *(const float2*)(g_Q + (size_t)(c * S_ + s) * 64 + lane * 2);
            float pe = Qr.x * ri;
            float po = Qr.y * ri;
            pe += __shfl_xor_sync(FULLMASK, pe, 4);
            pe += __shfl_xor_sync(FULLMASK, pe, 8);
            pe += __shfl_xor_sync(FULLMASK, pe, 16);
            po += __shfl_xor_sync(FULLMASK, po, 4);
            po += __shfl_xor_sync(FULLMASK, po, 8);
            po += __shfl_xor_sync(FULLMASK, po, 16);
            float re = __shfl_sync(FULLMASK, pe, i >> 1);
            float ro = __shfl_sync(FULLMASK, po, i >> 1);
            float rn = (i & 1) ? ro : re;
            float m = fmaxf(pe, po);
            m = fmaxf(m, __shfl_xor_sync(FULLMASK, m, 1));
            m = fmaxf(m, __shfl_xor_sync(FULLMASK, m, 2));
            ri = rn * rcpf(m);
            if (q == 0) g_Rb[(size_t)(c * S_ + s) * 8 + i] = ri;
        }
    }
}

// ---------------------------------------------------------------------------
// pass3 (fused fw+bw): 32-step log2-space recursion per (chain,segment).
// Emits UNNORMALIZED anchored values into g_fwu/g_bwu. 32-bit incremental ptrs.
// ---------------------------------------------------------------------------
__global__ void __launch_bounds__(128) pass3_kernel(
    const float* __restrict__ la, const float* __restrict__ lb,
    const float* __restrict__ lz)
{
    const int w    = blockIdx.x * 4 + (threadIdx.x >> 5);
    const int lane = threadIdx.x & 31;
    const int ii   = lane & 3;
    const int rr   = lane >> 2;
    const bool is_bw = (w >= C_ * S_);
    const int ws = is_bw ? w - C_ * S_ : w;
    const int c = ws >> 5, s = ws & 31;
    const int b = c >> 6, n = c & 63;
    const int tile0 = b * TN + n;
    const int sel0 = ii * 8, sel1 = ii * 8 + 4;

    if (!is_bw) {
        float prev;
        int t0;
        if (s == 0) {
            prev = (lz[n * 8 + rr] + lb[tile0 * 8 + rr]) * L2E;
            if (ii == 0) g_fwu[tile0 * 8 + rr] = prev;
            t0 = 1;
        } else {
            prev = lg2f(g_Vb[(c * S_ + s) * 8 + rr]);
            t0 = s * L_;
        }
        const int t1 = s * L_ + L_ - 1;

        const float2* ap = (const float2*)la + (tile0 + t0 * N_) * 32 + lane;
        const float*  bp = lb + (tile0 + t0 * N_) * 8 + rr;
        float*        op = g_fwu + (tile0 + t0 * N_) * 8 + rr;

        for (int t = t0; t <= t1; t++) {
            float2 av = *ap;
            float  bv = *bp;
            ap += 32 * N_; bp += 8 * N_;
            float p0 = __shfl_sync(FULLMASK, prev, sel0);
            float p1 = __shfl_sync(FULLMASK, prev, sel1);
            float u0 = __shfl_sync(FULLMASK, prev, 0);
            float e = ex2f(fmaf(av.x, L2E, p0 - u0))
                    + ex2f(fmaf(av.y, L2E, p1 - u0));
            e += __shfl_xor_sync(FULLMASK, e, 1);
            e += __shfl_xor_sync(FULLMASK, e, 2);
            float uu = fmaf(bv, L2E, lg2f(e));
            prev = uu;
            if (ii == 0) *op = uu;
            op += 8 * N_;
        }
    } else {
        float prev;
        if (s == 31) {
            prev = 0.0f;
            if (ii == 0) g_bwu[(tile0 + 1023 * N_) * 8 + rr] = 0.0f;
        } else {
            prev = lg2f(g_Rb[(c * S_ + s + 1) * 8 + rr]);
            if (ii == 0) g_bwu[(tile0 + (s * L_ + L_ - 1) * N_) * 8 + rr] = prev;
        }
        const int th = s * L_ + L_ - 2;   // first t computed
        const int tl_ = s * L_;

        const float*  cp  = la + (tile0 + (th + 1) * N_) * 64 + ii * 16 + rr;
        const float2* bp2 = (const float2*)lb + (tile0 + (th + 1) * N_) * 4 + ii;
        float*        op  = g_bwu + (tile0 + th * N_) * 8 + rr;

        for (int t = th; t >= tl_; t--) {
            float  c0 = cp[0];          // a_{t+1}[2ii][j]
            float  c1 = cp[8];          // a_{t+1}[2ii+1][j]
            float2 bv = *bp2;
            cp  -= 64 * N_; bp2 -= 4 * N_;
            float p0 = __shfl_sync(FULLMASK, prev, sel0);
            float p1 = __shfl_sync(FULLMASK, prev, sel1);
            float u0 = __shfl_sync(FULLMASK, prev, 0);
            float e = ex2f(fmaf(c0 + bv.x, L2E, p0 - u0))
                    + ex2f(fmaf(c1 + bv.y, L2E, p1 - u0));
            e += __shfl_xor_sync(FULLMASK, e, 1);
            e += __shfl_xor_sync(FULLMASK, e, 2);
            float uu = lg2f(e);
            prev = uu;
            if (ii == 0) *op = uu;
            op -= 8 * N_;
        }
    }
}

// ---------------------------------------------------------------------------
// gamma: normalize fw/bw (final outputs) + gamma1 + gamma2.
// One warp = 4 consecutive-n tiles at one (b,t); 8-lane group per tile.
// ---------------------------------------------------------------------------
__global__ void __launch_bounds__(256) gamma_kernel(
    const float* __restrict__ la,
    const float* __restrict__ lb,
    float* __restrict__ fw,
    float* __restrict__ bwo,
    float* __restrict__ g1,
    float* __restrict__ g2)
{
    const int w    = blockIdx.x * (blockDim.x >> 5) + (threadIdx.x >> 5);
    const int lane = threadIdx.x & 31;
    const int grp  = lane >> 3;
    const int r    = lane & 7;

    const int nt    = w % (N_ / 4);
    const int btile = w / (N_ / 4);
    const int t     = btile % T_;
    const int b     = btile / T_;
    const int n     = nt * 4 + grp;
    const int base  = (b * T_ + t) * N_ + n;

    const float fu = g_fwu[base * 8 + r];   // log2, unnormalized (anchored)
    const float bu = g_bwu[base * 8 + r];

    // normalize fw -> output
    {
        float m = fu;
        m = fmaxf(m, __shfl_xor_sync(FULLMASK, m, 1));
        m = fmaxf(m, __shfl_xor_sync(FULLMASK, m, 2));
        m = fmaxf(m, __shfl_xor_sync(FULLMASK, m, 4));
        float e = ex2f(fu - m);
        e += __shfl_xor_sync(FULLMASK, e, 1);
        e += __shfl_xor_sync(FULLMASK, e, 2);
        e += __shfl_xor_sync(FULLMASK, e, 4);
        fw[base * 8 + r] = (fu - m - lg2f(e)) * LN2;
    }
    // normalize bw -> output (t = T-1 stays raw zeros, per reference)
    {
        float m = bu;
        m = fmaxf(m, __shfl_xor_sync(FULLMASK, m, 1));
        m = fmaxf(m, __shfl_xor_sync(FULLMASK, m, 2));
        m = fmaxf(m, __shfl_xor_sync(FULLMASK, m, 4));
        float e = ex2f(bu - m);
        e += __shfl_xor_sync(FULLMASK, e, 1);
        e += __shfl_xor_sync(FULLMASK, e, 2);
        e += __shfl_xor_sync(FULLMASK, e, 4);
        bwo[base * 8 + r] = (t == T_ - 1) ? 0.0f : (bu - m - lg2f(e)) * LN2;
    }

    // gamma1 = normalize(fu + bu)  (shifts cancel)
    {
        float v = fu + bu;
        float m = v;
        m = fmaxf(m, __shfl_xor_sync(FULLMASK, m, 1));
        m = fmaxf(m, __shfl_xor_sync(FULLMASK, m, 2));
        m = fmaxf(m, __shfl_xor_sync(FULLMASK, m, 4));
        float e = ex2f(v - m);
        e += __shfl_xor_sync(FULLMASK, e, 1);
        e += __shfl_xor_sync(FULLMASK, e, 2);
        e += __shfl_xor_sync(FULLMASK, e, 4);
        g1[base * 8 + r] = (v - m - lg2f(e)) * LN2;
    }

    float4* g2p = (float4*)(g2 + (long long)base * 64 + r * 8);
    if (t == 0) {                       // warp-uniform
        float4 z = make_float4(0.f, 0.f, 0.f, 0.f);
        g2p[0] = z;
        g2p[1] = z;
        return;
    }

    const float fwp = g_fwu[(base - N_) * 8 + r];            // log2, shift cancels
    const float s2  = fmaf(lb[base * 8 + r], L2E, bu);       // bu + lb*L2E
    const float4* pa = (const float4*)(la + (long long)base * 64 + r * 8);
    float av[8];
    *(float4*)&av[0] = pa[0];
    *(float4*)&av[4] = pa[1];

    float g[8];
    #pragma unroll
    for (int j = 0; j < 8; j++)
        g[j] = fmaf(av[j], L2E, __shfl_sync(FULLMASK, fwp, j, 8) + s2);

    float m = g[0];
    #pragma unroll
    for (int j = 1; j < 8; j++) m = fmaxf(m, g[j]);
    m = fmaxf(m, __shfl_xor_sync(FULLMASK, m, 1));
    m = fmaxf(m, __shfl_xor_sync(FULLMASK, m, 2));
    m = fmaxf(m, __shfl_xor_sync(FULLMASK, m, 4));
    float e = 0.f;
    #pragma unroll
    for (int j = 0; j < 8; j++) e += ex2f(g[j] - m);
    e += __shfl_xor_sync(FULLMASK, e, 1);
    e += __shfl_xor_sync(FULLMASK, e, 2);
    e += __shfl_xor_sync(FULLMASK, e, 4);
    const float lse = m + lg2f(e);

    float4 o0 = make_float4((g[0] - lse) * LN2, (g[1] - lse) * LN2,
                            (g[2] - lse) * LN2, (g[3] - lse) * LN2);
    float4 o1 = make_float4((g[4] - lse) * LN2, (g[5] - lse) * LN2,
                            (g[6] - lse) * LN2, (g[7] - lse) * LN2);
    g2p[0] = o0;
    g2p[1] = o1;
}

extern "C" void kernel_launch(void* const* d_in, const int* in_sizes, int n_in,
                              void* d_out, int out_size) {
    const float* la = (const float*)d_in[0];   // log_a  (B,T,N,K,K)
    const float* lb = (const float*)d_in[1];   // log_b  (B,T,N,K)
    const float* lz = (const float*)d_in[2];   // logprob_z1 (N,K)

    float* out = (float*)d_out;
    float* fw = out;
    float* bw = fw + BTNK;
    float* g1 = bw + BTNK;
    float* g2 = g1 + BTNK;

    pass1_kernel<<<(C_ * S_) / 4, 128>>>(la, lb);        // 16384 warps
    pass2_kernel<<<(2 * C_) / 4, 128>>>(lb, lz);         // 1024 warps
    pass3_kernel<<<(2 * C_ * S_) / 4, 128>>>(la, lb, lz);// 32768 warps (fw+bw)
    gamma_kernel<<<(B_ * T_ * (N_ / 4)) / 8, 256>>>(la, lb, fw, bw, g1, g2);
}